// round 16
// baseline (speedup 1.0000x reference)
#include <cuda_runtime.h>
#include <cuda_bf16.h>

#define NN 2048
#define NM1 2047
#define NSUP 1536
#define CLS 5

typedef unsigned long long u64;

__device__ __forceinline__ u64 add2(u64 a, u64 b) {
    u64 d; asm("add.rn.f32x2 %0, %1, %2;" : "=l"(d) : "l"(a), "l"(b)); return d;
}
__device__ __forceinline__ u64 fma2(u64 a, u64 b, u64 c) {
    u64 d; asm("fma.rn.f32x2 %0, %1, %2, %3;" : "=l"(d) : "l"(a), "l"(b), "l"(c)); return d;
}
__device__ __forceinline__ float lo32(u64 v) { return __uint_as_float((unsigned)(v & 0xffffffffu)); }
__device__ __forceinline__ float hi32(u64 v) { return __uint_as_float((unsigned)(v >> 32)); }
__device__ __forceinline__ u64 dupf(float a) {
    unsigned u = __float_as_uint(a);
    return ((u64)u << 32) | u;
}

// ------------------- scratch (device globals, no allocs) -------------------
__device__ float g_xw[2 * NN * 32];     // holds dis[r] * (X@W)  (pre-scaled)
__device__ float g_deg[2 * NN];
__device__ float g_acc1[2 * NN * 32];
__device__ float g_tefe[NN * 64];
__device__ float g_Aw[NN * NN];
__device__ float g_degc[NN];
__device__ float g_fcw[NN * 128];
__device__ float g_embp[16 * NN * 128];
__device__ float g_cols[8];

// ------------------- launch 0: init -------------------
__global__ void k_init(const int* __restrict__ labels) {
    int idx = blockIdx.x * blockDim.x + threadIdx.x;
    int stride = gridDim.x * blockDim.x;
    for (int i = idx; i < 2 * NN * 32; i += stride) g_acc1[i] = 0.f;
    for (int i = idx; i < 2 * NN; i += stride) g_deg[i] = 0.f;
    for (int i = idx; i < NN; i += stride) g_degc[i] = 0.f;
    if (blockIdx.x == 0) {
        if (threadIdx.x < 8) g_cols[threadIdx.x] = 0.f;
        __syncthreads();
        for (int i = threadIdx.x; i < NN; i += blockDim.x) g_cols[labels[i]] = 1.0f;
    }
}

// ------------------- launch 1: deg[c] = sum_r A[c,r] -------------------
__global__ void k_deg(const float* __restrict__ wt, const float* __restrict__ wf) {
    int branch = blockIdx.z;
    const float* w = branch ? wf : wt;
    int c = blockIdx.x * 256 + threadIdx.x;
    int r0 = blockIdx.y * 64;
    float s = 0.f;
#pragma unroll 4
    for (int r = r0; r < r0 + 64; r++) {
        if (r != c) s += w[r * NM1 + c - (c > r)];
    }
    atomicAdd(&g_deg[branch * NN + c], s);
}

// ------------------- launch 2: XW = dis * (X @ W)  (pre-scaled) -------------------
__global__ void k_xw(const float* __restrict__ X0, const float* __restrict__ X1,
                     const float* __restrict__ W0, const float* __restrict__ W1) {
    int branch = blockIdx.y;
    const float* X = branch ? X1 : X0;
    const float* W = branch ? W1 : W0;
    __shared__ float Ws[256 * 32];
    __shared__ float Xs[64][33];
    for (int e = threadIdx.x; e < 256 * 32; e += 256) Ws[e] = W[e];
    int r0 = blockIdx.x * 64;
    int f = threadIdx.x & 31;
    int rg = threadIdx.x >> 5;
    float acc[8] = {};
    for (int k0 = 0; k0 < 256; k0 += 32) {
        __syncthreads();
        for (int e = threadIdx.x; e < 64 * 32; e += 256) {
            int i = e >> 5, kk = e & 31;
            Xs[i][kk] = X[(r0 + i) * 256 + k0 + kk];
        }
        __syncthreads();
#pragma unroll
        for (int kk = 0; kk < 32; kk++) {
            float wv = Ws[(k0 + kk) * 32 + f];
#pragma unroll
            for (int l = 0; l < 8; l++)
                acc[l] += Xs[rg + 8 * l][kk] * wv;
        }
    }
#pragma unroll
    for (int l = 0; l < 8; l++) {
        int r = r0 + rg + 8 * l;
        float dis = rsqrtf(1.0f + g_deg[branch * NN + r]);
        g_xw[branch * NN * 32 + r * 32 + f] = dis * acc[l];
    }
}

// ------------------- launch 3 (PROFILED): A @ xwd, cp.async double-buffered -------------------
// grid (16, 16, 2); block 256. c-tile 128, r-chunk 128 in 4 tiles of 32.
__global__ void __launch_bounds__(256) k_gcn1(const float* __restrict__ tw,
                                              const float* __restrict__ fw) {
    int br = blockIdx.z;
    const float* w = br ? fw : tw;
    __shared__ float As[2][32][128];               // 32KB
    __shared__ __align__(16) float ys[2][32][32];  // 8KB
    int tid = threadIdx.x;
    int cl = tid & 127;
    int f0 = (tid >> 7) * 16;
    int c0 = blockIdx.x * 128;
    int rbase = blockIdx.y * 128;
    const float* xwd = &g_xw[br * NN * 32];

    unsigned as0 = (unsigned)__cvta_generic_to_shared(&As[0][0][0]);
    unsigned ys0 = (unsigned)__cvta_generic_to_shared(&ys[0][0][0]);

    auto issue = [&](int t, int buf) {
        int r0 = rbase + 32 * t;
        unsigned as_base = as0 + (unsigned)buf * (32 * 128 * 4);
#pragma unroll
        for (int k = 0; k < 16; k++) {
            int e = tid + k * 256;
            int j = e >> 7, i = e & 127;
            int r = r0 + j, c = c0 + i;
            const float* src = &w[r * NM1 + c - (c > r)];
            unsigned dst = as_base + (unsigned)(e * 4);
            int sz = (c == r) ? 0 : 4;      // zero-fill the diagonal
            asm volatile("cp.async.ca.shared.global [%0], [%1], 4, %2;"
                         :: "r"(dst), "l"(src), "r"(sz));
        }
        {
            int j = tid >> 3, i4 = (tid & 7) * 4;
            const float* src = &xwd[(r0 + j) * 32 + i4];
            unsigned dst = ys0 + (unsigned)buf * (32 * 32 * 4) + (unsigned)(tid * 16);
            asm volatile("cp.async.cg.shared.global [%0], [%1], 16;"
                         :: "r"(dst), "l"(src));
        }
        asm volatile("cp.async.commit_group;");
    };

    issue(0, 0);
    u64 acc2[8] = {};
#pragma unroll
    for (int t = 0; t < 4; t++) {
        int buf = t & 1;
        if (t < 3) {
            issue(t + 1, buf ^ 1);
            asm volatile("cp.async.wait_group 1;");
        } else {
            asm volatile("cp.async.wait_group 0;");
        }
        __syncthreads();
#pragma unroll
        for (int j = 0; j < 32; j++) {
            u64 aa = dupf(As[buf][j][cl]);
            const ulonglong2* yp = (const ulonglong2*)&ys[buf][j][f0];
            ulonglong2 y01 = yp[0];
            ulonglong2 y23 = yp[1];
            acc2[0] = fma2(aa, y01.x, acc2[0]);
            acc2[1] = fma2(aa, y01.y, acc2[1]);
            acc2[2] = fma2(aa, y23.x, acc2[2]);
            acc2[3] = fma2(aa, y23.y, acc2[3]);
            const ulonglong2* yq = (const ulonglong2*)&ys[buf][j][f0 + 8];
            ulonglong2 y45 = yq[0];
            ulonglong2 y67 = yq[1];
            acc2[4] = fma2(aa, y45.x, acc2[4]);
            acc2[5] = fma2(aa, y45.y, acc2[5]);
            acc2[6] = fma2(aa, y67.x, acc2[6]);
            acc2[7] = fma2(aa, y67.y, acc2[7]);
        }
        __syncthreads();
    }
    float* dst = &g_acc1[br * NN * 32 + (c0 + cl) * 32 + f0];
#pragma unroll
    for (int k = 0; k < 8; k++) {
        atomicAdd(dst + 2 * k, lo32(acc2[k]));
        atomicAdd(dst + 2 * k + 1, hi32(acc2[k]));
    }
}

// ------------------- launch 4: fin1 + fcw fused (uses pre-scaled xwd) -------------------
__global__ void k_fcwfin(const float* __restrict__ bt, const float* __restrict__ bf,
                         const float* __restrict__ Wc) {
    __shared__ float Wcs[64 * 128];
    __shared__ float Ts[16][64];
    __shared__ float ohs[128];
    int tid = threadIdx.x;
    int r0 = blockIdx.x * 16;
    for (int e = tid; e < 64 * 128; e += 256) Wcs[e] = Wc[e];
    if (tid < 128) {
        float s = 0.f;
#pragma unroll
        for (int c = 0; c < CLS; c++) s += g_cols[c] * Wc[(64 + c) * 128 + tid];
        ohs[tid] = s;
    }
    for (int e = tid; e < 16 * 64; e += 256) {
        int i = e >> 6, q = e & 63;
        int branch = q >> 5, f = q & 31;
        int c = r0 + i;
        float b = branch ? bf[f] : bt[f];
        float d = rsqrtf(1.0f + g_deg[branch * NN + c]);
        // xwd = d*xw  =>  d*acc1 + d*xwd + b  ==  d*acc1 + d^2*xw + b
        float v = d * g_acc1[branch * NN * 32 + c * 32 + f]
                + d * g_xw[branch * NN * 32 + c * 32 + f] + b;
        v = v > 0.f ? v : 0.01f * v;
        Ts[i][q] = v;
        g_tefe[c * 64 + q] = v;
    }
    __syncthreads();
    int f = tid & 127, rh = tid >> 7;
    for (int i = rh * 8; i < rh * 8 + 8; i++) {
        int r = r0 + i;
        float acc = (r < NSUP) ? ohs[f] : 0.f;
#pragma unroll
        for (int k = 0; k < 64; k++) acc += Ts[i][k] * Wcs[k * 128 + f];
        g_fcw[r * 128 + f] = acc;
    }
}

// ------------------- launch 5: dist, triangular grid, 512 threads (proven best) -------------------
__global__ void __launch_bounds__(512, 3) k_dist() {
    int kb = blockIdx.x;
    int bi = (int)(0.5f * (65.0f - sqrtf(65.0f * 65.0f - 8.0f * (float)kb)));
    while ((bi + 1) * (65 - (bi + 1)) / 2 <= kb) bi++;
    while (bi * (65 - bi) / 2 > kb) bi--;
    int bj = bi + (kb - bi * (65 - bi) / 2);
    bool diag = (bi == bj);
    __shared__ __align__(16) float Si[64][68];
    __shared__ __align__(16) float Sjn[64][68];
    __shared__ float scs[64];
    int tid = threadIdx.x;
    int i0 = bi * 64, j0 = bj * 64;
    for (int e = tid; e < 64 * 16; e += 512) {
        int r = e >> 4, d4 = (e & 15) * 4;
        *(float4*)&Si[r][d4] = *(const float4*)&g_tefe[(i0 + r) * 64 + d4];
        float4 b = *(const float4*)&g_tefe[(j0 + r) * 64 + d4];
        b.x = -b.x; b.y = -b.y; b.z = -b.z; b.w = -b.w;
        *(float4*)&Sjn[r][d4] = b;
    }
    if (tid < 64) scs[tid] = 0.f;
    __syncthreads();
    int jx = tid & 31, iy = tid >> 5;
    u64 acc[4][2] = {};
#pragma unroll
    for (int d = 0; d < 64; d += 4) {
        ulonglong2 b0 = *(const ulonglong2*)&Sjn[jx][d];
        ulonglong2 b1 = *(const ulonglong2*)&Sjn[jx + 32][d];
#pragma unroll
        for (int t = 0; t < 4; t++) {
            ulonglong2 a = *(const ulonglong2*)&Si[iy + 16 * t][d];
            u64 s0 = add2(a.x, b0.x) & 0x7FFFFFFF7FFFFFFFULL;
            u64 s1 = add2(a.y, b0.y) & 0x7FFFFFFF7FFFFFFFULL;
            acc[t][0] = add2(acc[t][0], s0);
            acc[t][0] = add2(acc[t][0], s1);
            u64 s2 = add2(a.x, b1.x) & 0x7FFFFFFF7FFFFFFFULL;
            u64 s3 = add2(a.y, b1.y) & 0x7FFFFFFF7FFFFFFFULL;
            acc[t][1] = add2(acc[t][1], s2);
            acc[t][1] = add2(acc[t][1], s3);
        }
    }
    __syncthreads();
    float* Vt = &Sjn[0][0];
    float colpart0 = 0.f, colpart1 = 0.f;
    int ja = j0 + jx, jb = j0 + jx + 32;
#pragma unroll
    for (int t = 0; t < 4; t++) {
        int il = iy + 16 * t;
        int i = i0 + il;
        float d0 = lo32(acc[t][0]) + hi32(acc[t][0]);
        float d1 = lo32(acc[t][1]) + hi32(acc[t][1]);
        float v0 = (i == ja) ? 0.f : __frcp_rn(d0 + 1e-5f);
        float v1 = (i == jb) ? 0.f : __frcp_rn(d1 + 1e-5f);
        g_Aw[i * NN + ja] = v0;
        g_Aw[i * NN + jb] = v1;
        Vt[jx * 67 + il] = v0;
        Vt[(jx + 32) * 67 + il] = v1;
        colpart0 += v0; colpart1 += v1;
        float rs = v0 + v1;
#pragma unroll
        for (int off = 16; off; off >>= 1)
            rs += __shfl_down_sync(0xffffffffu, rs, off);
        if (jx == 0) atomicAdd(&g_degc[i], rs);
    }
    atomicAdd(&scs[jx], colpart0);
    atomicAdd(&scs[jx + 32], colpart1);
    __syncthreads();
    if (!diag) {
        if (tid < 64) atomicAdd(&g_degc[j0 + tid], scs[tid]);
        for (int e = tid; e < 64 * 64; e += 512) {
            int jl = e >> 6, il = e & 63;
            g_Aw[(j0 + jl) * NN + i0 + il] = Vt[jl * 67 + il];
        }
    }
}

// ------------------- launch 6: Aw @ (disc * fcw), 512 CTAs, partials -------------------
__global__ void __launch_bounds__(256) k_gcn2() {
    __shared__ __align__(16) float Aws[32][68];
    __shared__ __align__(16) float y2s[32][128];
    int tid = threadIdx.x;
    int c0 = blockIdx.x * 64;
    int rbase = blockIdx.y * 128;
    int fq = tid & 31;
    int cg = tid >> 5;
    int f0 = fq * 4;
    u64 acc[8][2] = {};
    for (int r0 = rbase; r0 < rbase + 128; r0 += 32) {
        __syncthreads();
        for (int e = tid; e < 64 * 32; e += 256) {
            int i = e >> 5, j = e & 31;
            Aws[j][i] = g_Aw[(c0 + i) * NN + r0 + j];
        }
        for (int e = tid; e < 32 * 128; e += 256) {
            int j = e >> 7, f = e & 127;
            int r = r0 + j;
            float disc = rsqrtf(1.0f + g_degc[r]);
            y2s[j][f] = disc * g_fcw[r * 128 + f];
        }
        __syncthreads();
#pragma unroll
        for (int j = 0; j < 32; j++) {
            float4 a0 = *(const float4*)&Aws[j][cg * 8];
            float4 a1 = *(const float4*)&Aws[j][cg * 8 + 4];
            ulonglong2 bv = *(const ulonglong2*)&y2s[j][f0];
            u64 d0 = dupf(a0.x), d1 = dupf(a0.y), d2 = dupf(a0.z), d3 = dupf(a0.w);
            u64 d4 = dupf(a1.x), d5 = dupf(a1.y), d6 = dupf(a1.z), d7 = dupf(a1.w);
            acc[0][0] = fma2(d0, bv.x, acc[0][0]); acc[0][1] = fma2(d0, bv.y, acc[0][1]);
            acc[1][0] = fma2(d1, bv.x, acc[1][0]); acc[1][1] = fma2(d1, bv.y, acc[1][1]);
            acc[2][0] = fma2(d2, bv.x, acc[2][0]); acc[2][1] = fma2(d2, bv.y, acc[2][1]);
            acc[3][0] = fma2(d3, bv.x, acc[3][0]); acc[3][1] = fma2(d3, bv.y, acc[3][1]);
            acc[4][0] = fma2(d4, bv.x, acc[4][0]); acc[4][1] = fma2(d4, bv.y, acc[4][1]);
            acc[5][0] = fma2(d5, bv.x, acc[5][0]); acc[5][1] = fma2(d5, bv.y, acc[5][1]);
            acc[6][0] = fma2(d6, bv.x, acc[6][0]); acc[6][1] = fma2(d6, bv.y, acc[6][1]);
            acc[7][0] = fma2(d7, bv.x, acc[7][0]); acc[7][1] = fma2(d7, bv.y, acc[7][1]);
        }
    }
    int p = blockIdx.y;
#pragma unroll
    for (int t = 0; t < 8; t++) {
        int c = c0 + cg * 8 + t;
        u64* dst = (u64*)&g_embp[((size_t)p * NN + c) * 128 + f0];
        dst[0] = acc[t][0];
        dst[1] = acc[t][1];
    }
}

// ------------------- launch 7: epilogue (sums 16 partials) -------------------
__global__ void k_out(const float* __restrict__ bc, const float* __restrict__ Wo,
                      const float* __restrict__ bo, float* __restrict__ out) {
    __shared__ float Wos[128 * CLS];
    int tid = threadIdx.x;
    for (int e = tid; e < 128 * CLS; e += 256) Wos[e] = Wo[e];
    __syncthreads();
    int wid = tid >> 5, l = tid & 31;
    int row = blockIdx.x * 8 + wid;
    float dc = rsqrtf(1.0f + g_degc[row]);
    float dc2 = dc * dc;
    float o[CLS] = {};
#pragma unroll
    for (int t = 0; t < 4; t++) {
        int f = l + 32 * t;
        float s = 0.f;
#pragma unroll
        for (int p = 0; p < 16; p++) s += g_embp[((size_t)p * NN + row) * 128 + f];
        float e = dc * s + dc2 * g_fcw[row * 128 + f] + bc[f];
        e = e > 0.f ? e : 0.01f * e;
#pragma unroll
        for (int q = 0; q < CLS; q++) o[q] += e * Wos[f * CLS + q];
    }
#pragma unroll
    for (int q = 0; q < CLS; q++) {
#pragma unroll
        for (int off = 16; off; off >>= 1)
            o[q] += __shfl_down_sync(0xffffffffu, o[q], off);
    }
    if (l == 0) {
#pragma unroll
        for (int q = 0; q < CLS; q++) out[row * CLS + q] = o[q] + bo[q];
    }
}

// ------------------- launch -------------------
extern "C" void kernel_launch(void* const* d_in, const int* in_sizes, int n_in,
                              void* d_out, int out_size) {
    int cur = 0;
    auto nxt = [&]() -> const void* {
        while (cur < n_in && in_sizes[cur] == 1) cur++;
        return d_in[cur++];
    };
    const float* tf     = (const float*)nxt();
    (void)nxt();                                 // edge_index (structural, unused)
    const float* tw     = (const float*)nxt();
    const float* ff     = (const float*)nxt();
    const float* fw     = (const float*)nxt();
    const int*   labels = (const int*)nxt();
    const float* Wt     = (const float*)nxt();
    const float* bt     = (const float*)nxt();
    const float* Wf     = (const float*)nxt();
    const float* bf     = (const float*)nxt();
    const float* Wc     = (const float*)nxt();
    const float* bc     = (const float*)nxt();
    const float* Wo     = (const float*)nxt();
    const float* bo     = (const float*)nxt();
    float* out = (float*)d_out;

    k_init<<<64, 256>>>(labels);                  // idx 0
    k_deg<<<dim3(8, 32, 2), 256>>>(tw, fw);       // idx 1
    k_xw<<<dim3(32, 2), 256>>>(tf, ff, Wt, Wf);   // idx 2
    k_gcn1<<<dim3(16, 16, 2), 256>>>(tw, fw);     // idx 3  <- ncu capture slot
    k_fcwfin<<<128, 256>>>(bt, bf, Wc);           // idx 4
    k_dist<<<528, 512>>>();                       // idx 5
    k_gcn2<<<dim3(32, 16), 256>>>();              // idx 6
    k_out<<<256, 256>>>(bc, Wo, bo, out);         // idx 7
}

// round 17
// speedup vs baseline: 1.0829x; 1.0829x over previous
#include <cuda_runtime.h>
#include <cuda_bf16.h>

#define NN 2048
#define NM1 2047
#define NSUP 1536
#define CLS 5

typedef unsigned long long u64;

__device__ __forceinline__ u64 add2(u64 a, u64 b) {
    u64 d; asm("add.rn.f32x2 %0, %1, %2;" : "=l"(d) : "l"(a), "l"(b)); return d;
}
__device__ __forceinline__ u64 fma2(u64 a, u64 b, u64 c) {
    u64 d; asm("fma.rn.f32x2 %0, %1, %2, %3;" : "=l"(d) : "l"(a), "l"(b), "l"(c)); return d;
}
__device__ __forceinline__ float lo32(u64 v) { return __uint_as_float((unsigned)(v & 0xffffffffu)); }
__device__ __forceinline__ float hi32(u64 v) { return __uint_as_float((unsigned)(v >> 32)); }
__device__ __forceinline__ u64 dupf(float a) {
    unsigned u = __float_as_uint(a);
    return ((u64)u << 32) | u;
}

// ------------------- scratch (device globals, no allocs) -------------------
__device__ float g_xw[2 * NN * 32];
__device__ float g_deg[2 * NN];
__device__ float g_acc1[2 * NN * 32];
__device__ float g_tefe[NN * 64];
__device__ float g_Aw[NN * NN];
__device__ float g_degc[NN];
__device__ float g_fcw[NN * 128];
__device__ float g_embp[16 * NN * 128];
__device__ float g_cols[8];

// ------------------- launch 0: init -------------------
__global__ void k_init(const int* __restrict__ labels) {
    int idx = blockIdx.x * blockDim.x + threadIdx.x;
    int stride = gridDim.x * blockDim.x;
    for (int i = idx; i < 2 * NN * 32; i += stride) g_acc1[i] = 0.f;
    for (int i = idx; i < 2 * NN; i += stride) g_deg[i] = 0.f;
    for (int i = idx; i < NN; i += stride) g_degc[i] = 0.f;
    if (blockIdx.x == 0) {
        if (threadIdx.x < 8) g_cols[threadIdx.x] = 0.f;
        __syncthreads();
        for (int i = threadIdx.x; i < NN; i += blockDim.x) g_cols[labels[i]] = 1.0f;
    }
}

// ------------------- launch 1: XW = X @ W -------------------
__global__ void k_xw(const float* __restrict__ X0, const float* __restrict__ X1,
                     const float* __restrict__ W0, const float* __restrict__ W1) {
    int branch = blockIdx.y;
    const float* X = branch ? X1 : X0;
    const float* W = branch ? W1 : W0;
    __shared__ float Ws[256 * 32];
    __shared__ float Xs[64][33];
    for (int e = threadIdx.x; e < 256 * 32; e += 256) Ws[e] = W[e];
    int r0 = blockIdx.x * 64;
    int f = threadIdx.x & 31;
    int rg = threadIdx.x >> 5;
    float acc[8] = {};
    for (int k0 = 0; k0 < 256; k0 += 32) {
        __syncthreads();
        for (int e = threadIdx.x; e < 64 * 32; e += 256) {
            int i = e >> 5, kk = e & 31;
            Xs[i][kk] = X[(r0 + i) * 256 + k0 + kk];
        }
        __syncthreads();
#pragma unroll
        for (int kk = 0; kk < 32; kk++) {
            float wv = Ws[(k0 + kk) * 32 + f];
#pragma unroll
            for (int l = 0; l < 8; l++)
                acc[l] += Xs[rg + 8 * l][kk] * wv;
        }
    }
#pragma unroll
    for (int l = 0; l < 8; l++)
        g_xw[branch * NN * 32 + (r0 + rg + 8 * l) * 32 + f] = acc[l];
}

// ------------------- launch 2: deg[c] = sum_r A[c,r] -------------------
__global__ void k_deg(const float* __restrict__ wt, const float* __restrict__ wf) {
    int branch = blockIdx.z;
    const float* w = branch ? wf : wt;
    int c = blockIdx.x * 256 + threadIdx.x;
    int r0 = blockIdx.y * 64;
    float s = 0.f;
#pragma unroll 4
    for (int r = r0; r < r0 + 64; r++) {
        if (r != c) s += w[r * NM1 + c - (c > r)];
    }
    atomicAdd(&g_deg[branch * NN + c], s);
}

// ------------------- launch 3 (PROFILED): A @ (dis*xw), cp.async A-tile only -------------------
// grid (16, 16, 2); block 256; regs capped (4 blocks/SM, single wave).
__global__ void __launch_bounds__(256, 4) k_gcn1(const float* __restrict__ tw,
                                                 const float* __restrict__ fw) {
    int br = blockIdx.z;
    const float* w = br ? fw : tw;
    __shared__ float As[2][32][128];               // 32KB, double-buffered via cp.async
    __shared__ __align__(16) float ys[32][32];     // 4KB, synchronous fill
    int tid = threadIdx.x;
    int cl = tid & 127;
    int f0 = (tid >> 7) * 16;
    int c0 = blockIdx.x * 128;
    int rbase = blockIdx.y * 128;

    unsigned as0 = (unsigned)__cvta_generic_to_shared(&As[0][0][0]);

    auto issueA = [&](int t, int buf) {
        int r0 = rbase + 32 * t;
        unsigned base = as0 + (unsigned)buf * (32 * 128 * 4);
#pragma unroll
        for (int k = 0; k < 16; k++) {
            int e = tid + k * 256;
            int j = e >> 7, i = e & 127;
            int r = r0 + j, c = c0 + i;
            const float* src = &w[r * NM1 + c - (c > r)];
            unsigned dst = base + (unsigned)(e * 4);
            int sz = (c == r) ? 0 : 4;      // zero-fill the diagonal
            asm volatile("cp.async.ca.shared.global [%0], [%1], 4, %2;"
                         :: "r"(dst), "l"(src), "r"(sz));
        }
        asm volatile("cp.async.commit_group;");
    };

    issueA(0, 0);
    u64 acc2[8] = {};
    for (int t = 0; t < 4; t++) {
        int buf = t & 1;
        if (t < 3) issueA(t + 1, buf ^ 1);
        // synchronous ys fill for tile t (overlaps the in-flight cp.async group)
        {
            int r0 = rbase + 32 * t;
            for (int e = tid; e < 32 * 32; e += 256) {
                int j = e >> 5, f = e & 31;
                int r = r0 + j;
                float dis = rsqrtf(1.0f + g_deg[br * NN + r]);
                ys[j][f] = dis * g_xw[br * NN * 32 + r * 32 + f];
            }
        }
        if (t < 3) { asm volatile("cp.async.wait_group 1;"); }
        else       { asm volatile("cp.async.wait_group 0;"); }
        __syncthreads();
#pragma unroll
        for (int j = 0; j < 32; j++) {
            u64 aa = dupf(As[buf][j][cl]);
            const ulonglong2* yp = (const ulonglong2*)&ys[j][f0];
            ulonglong2 y01 = yp[0];
            ulonglong2 y23 = yp[1];
            acc2[0] = fma2(aa, y01.x, acc2[0]);
            acc2[1] = fma2(aa, y01.y, acc2[1]);
            acc2[2] = fma2(aa, y23.x, acc2[2]);
            acc2[3] = fma2(aa, y23.y, acc2[3]);
            const ulonglong2* yq = (const ulonglong2*)&ys[j][f0 + 8];
            ulonglong2 y45 = yq[0];
            ulonglong2 y67 = yq[1];
            acc2[4] = fma2(aa, y45.x, acc2[4]);
            acc2[5] = fma2(aa, y45.y, acc2[5]);
            acc2[6] = fma2(aa, y67.x, acc2[6]);
            acc2[7] = fma2(aa, y67.y, acc2[7]);
        }
        __syncthreads();
    }
    float* dst = &g_acc1[br * NN * 32 + (c0 + cl) * 32 + f0];
#pragma unroll
    for (int k = 0; k < 8; k++) {
        atomicAdd(dst + 2 * k, lo32(acc2[k]));
        atomicAdd(dst + 2 * k + 1, hi32(acc2[k]));
    }
}

// ------------------- launch 4: fin1 + fcw fused -------------------
__global__ void k_fcwfin(const float* __restrict__ bt, const float* __restrict__ bf,
                         const float* __restrict__ Wc) {
    __shared__ float Wcs[64 * 128];
    __shared__ float Ts[16][64];
    __shared__ float ohs[128];
    int tid = threadIdx.x;
    int r0 = blockIdx.x * 16;
    for (int e = tid; e < 64 * 128; e += 256) Wcs[e] = Wc[e];
    if (tid < 128) {
        float s = 0.f;
#pragma unroll
        for (int c = 0; c < CLS; c++) s += g_cols[c] * Wc[(64 + c) * 128 + tid];
        ohs[tid] = s;
    }
    for (int e = tid; e < 16 * 64; e += 256) {
        int i = e >> 6, q = e & 63;
        int branch = q >> 5, f = q & 31;
        int c = r0 + i;
        float b = branch ? bf[f] : bt[f];
        float d = rsqrtf(1.0f + g_deg[branch * NN + c]);
        float v = d * g_acc1[branch * NN * 32 + c * 32 + f]
                + d * d * g_xw[branch * NN * 32 + c * 32 + f] + b;
        v = v > 0.f ? v : 0.01f * v;
        Ts[i][q] = v;
        g_tefe[c * 64 + q] = v;
    }
    __syncthreads();
    int f = tid & 127, rh = tid >> 7;
    for (int i = rh * 8; i < rh * 8 + 8; i++) {
        int r = r0 + i;
        float acc = (r < NSUP) ? ohs[f] : 0.f;
#pragma unroll
        for (int k = 0; k < 64; k++) acc += Ts[i][k] * Wcs[k * 128 + f];
        g_fcw[r * 128 + f] = acc;
    }
}

// ------------------- launch 5: dist, triangular grid, 512 threads (proven best) -------------------
__global__ void __launch_bounds__(512, 3) k_dist() {
    int kb = blockIdx.x;
    int bi = (int)(0.5f * (65.0f - sqrtf(65.0f * 65.0f - 8.0f * (float)kb)));
    while ((bi + 1) * (65 - (bi + 1)) / 2 <= kb) bi++;
    while (bi * (65 - bi) / 2 > kb) bi--;
    int bj = bi + (kb - bi * (65 - bi) / 2);
    bool diag = (bi == bj);
    __shared__ __align__(16) float Si[64][68];
    __shared__ __align__(16) float Sjn[64][68];
    __shared__ float scs[64];
    int tid = threadIdx.x;
    int i0 = bi * 64, j0 = bj * 64;
    for (int e = tid; e < 64 * 16; e += 512) {
        int r = e >> 4, d4 = (e & 15) * 4;
        *(float4*)&Si[r][d4] = *(const float4*)&g_tefe[(i0 + r) * 64 + d4];
        float4 b = *(const float4*)&g_tefe[(j0 + r) * 64 + d4];
        b.x = -b.x; b.y = -b.y; b.z = -b.z; b.w = -b.w;
        *(float4*)&Sjn[r][d4] = b;
    }
    if (tid < 64) scs[tid] = 0.f;
    __syncthreads();
    int jx = tid & 31, iy = tid >> 5;
    u64 acc[4][2] = {};
#pragma unroll
    for (int d = 0; d < 64; d += 4) {
        ulonglong2 b0 = *(const ulonglong2*)&Sjn[jx][d];
        ulonglong2 b1 = *(const ulonglong2*)&Sjn[jx + 32][d];
#pragma unroll
        for (int t = 0; t < 4; t++) {
            ulonglong2 a = *(const ulonglong2*)&Si[iy + 16 * t][d];
            u64 s0 = add2(a.x, b0.x) & 0x7FFFFFFF7FFFFFFFULL;
            u64 s1 = add2(a.y, b0.y) & 0x7FFFFFFF7FFFFFFFULL;
            acc[t][0] = add2(acc[t][0], s0);
            acc[t][0] = add2(acc[t][0], s1);
            u64 s2 = add2(a.x, b1.x) & 0x7FFFFFFF7FFFFFFFULL;
            u64 s3 = add2(a.y, b1.y) & 0x7FFFFFFF7FFFFFFFULL;
            acc[t][1] = add2(acc[t][1], s2);
            acc[t][1] = add2(acc[t][1], s3);
        }
    }
    __syncthreads();
    float* Vt = &Sjn[0][0];
    float colpart0 = 0.f, colpart1 = 0.f;
    int ja = j0 + jx, jb = j0 + jx + 32;
#pragma unroll
    for (int t = 0; t < 4; t++) {
        int il = iy + 16 * t;
        int i = i0 + il;
        float d0 = lo32(acc[t][0]) + hi32(acc[t][0]);
        float d1 = lo32(acc[t][1]) + hi32(acc[t][1]);
        float v0 = (i == ja) ? 0.f : __frcp_rn(d0 + 1e-5f);
        float v1 = (i == jb) ? 0.f : __frcp_rn(d1 + 1e-5f);
        g_Aw[i * NN + ja] = v0;
        g_Aw[i * NN + jb] = v1;
        Vt[jx * 67 + il] = v0;
        Vt[(jx + 32) * 67 + il] = v1;
        colpart0 += v0; colpart1 += v1;
        float rs = v0 + v1;
#pragma unroll
        for (int off = 16; off; off >>= 1)
            rs += __shfl_down_sync(0xffffffffu, rs, off);
        if (jx == 0) atomicAdd(&g_degc[i], rs);
    }
    atomicAdd(&scs[jx], colpart0);
    atomicAdd(&scs[jx + 32], colpart1);
    __syncthreads();
    if (!diag) {
        if (tid < 64) atomicAdd(&g_degc[j0 + tid], scs[tid]);
        for (int e = tid; e < 64 * 64; e += 512) {
            int jl = e >> 6, il = e & 63;
            g_Aw[(j0 + jl) * NN + i0 + il] = Vt[jl * 67 + il];
        }
    }
}

// ------------------- launch 6: Aw @ (disc * fcw), 512 CTAs, partials -------------------
__global__ void __launch_bounds__(256) k_gcn2() {
    __shared__ __align__(16) float Aws[32][68];
    __shared__ __align__(16) float y2s[32][128];
    int tid = threadIdx.x;
    int c0 = blockIdx.x * 64;
    int rbase = blockIdx.y * 128;
    int fq = tid & 31;
    int cg = tid >> 5;
    int f0 = fq * 4;
    u64 acc[8][2] = {};
    for (int r0 = rbase; r0 < rbase + 128; r0 += 32) {
        __syncthreads();
        for (int e = tid; e < 64 * 32; e += 256) {
            int i = e >> 5, j = e & 31;
            Aws[j][i] = g_Aw[(c0 + i) * NN + r0 + j];
        }
        for (int e = tid; e < 32 * 128; e += 256) {
            int j = e >> 7, f = e & 127;
            int r = r0 + j;
            float disc = rsqrtf(1.0f + g_degc[r]);
            y2s[j][f] = disc * g_fcw[r * 128 + f];
        }
        __syncthreads();
#pragma unroll
        for (int j = 0; j < 32; j++) {
            float4 a0 = *(const float4*)&Aws[j][cg * 8];
            float4 a1 = *(const float4*)&Aws[j][cg * 8 + 4];
            ulonglong2 bv = *(const ulonglong2*)&y2s[j][f0];
            u64 d0 = dupf(a0.x), d1 = dupf(a0.y), d2 = dupf(a0.z), d3 = dupf(a0.w);
            u64 d4 = dupf(a1.x), d5 = dupf(a1.y), d6 = dupf(a1.z), d7 = dupf(a1.w);
            acc[0][0] = fma2(d0, bv.x, acc[0][0]); acc[0][1] = fma2(d0, bv.y, acc[0][1]);
            acc[1][0] = fma2(d1, bv.x, acc[1][0]); acc[1][1] = fma2(d1, bv.y, acc[1][1]);
            acc[2][0] = fma2(d2, bv.x, acc[2][0]); acc[2][1] = fma2(d2, bv.y, acc[2][1]);
            acc[3][0] = fma2(d3, bv.x, acc[3][0]); acc[3][1] = fma2(d3, bv.y, acc[3][1]);
            acc[4][0] = fma2(d4, bv.x, acc[4][0]); acc[4][1] = fma2(d4, bv.y, acc[4][1]);
            acc[5][0] = fma2(d5, bv.x, acc[5][0]); acc[5][1] = fma2(d5, bv.y, acc[5][1]);
            acc[6][0] = fma2(d6, bv.x, acc[6][0]); acc[6][1] = fma2(d6, bv.y, acc[6][1]);
            acc[7][0] = fma2(d7, bv.x, acc[7][0]); acc[7][1] = fma2(d7, bv.y, acc[7][1]);
        }
    }
    int p = blockIdx.y;
#pragma unroll
    for (int t = 0; t < 8; t++) {
        int c = c0 + cg * 8 + t;
        u64* dst = (u64*)&g_embp[((size_t)p * NN + c) * 128 + f0];
        dst[0] = acc[t][0];
        dst[1] = acc[t][1];
    }
}

// ------------------- launch 7: epilogue (sums 16 partials) -------------------
__global__ void k_out(const float* __restrict__ bc, const float* __restrict__ Wo,
                      const float* __restrict__ bo, float* __restrict__ out) {
    __shared__ float Wos[128 * CLS];
    int tid = threadIdx.x;
    for (int e = tid; e < 128 * CLS; e += 256) Wos[e] = Wo[e];
    __syncthreads();
    int wid = tid >> 5, l = tid & 31;
    int row = blockIdx.x * 8 + wid;
    float dc = rsqrtf(1.0f + g_degc[row]);
    float dc2 = dc * dc;
    float o[CLS] = {};
#pragma unroll
    for (int t = 0; t < 4; t++) {
        int f = l + 32 * t;
        float s = 0.f;
#pragma unroll
        for (int p = 0; p < 16; p++) s += g_embp[((size_t)p * NN + row) * 128 + f];
        float e = dc * s + dc2 * g_fcw[row * 128 + f] + bc[f];
        e = e > 0.f ? e : 0.01f * e;
#pragma unroll
        for (int q = 0; q < CLS; q++) o[q] += e * Wos[f * CLS + q];
    }
#pragma unroll
    for (int q = 0; q < CLS; q++) {
#pragma unroll
        for (int off = 16; off; off >>= 1)
            o[q] += __shfl_down_sync(0xffffffffu, o[q], off);
    }
    if (l == 0) {
#pragma unroll
        for (int q = 0; q < CLS; q++) out[row * CLS + q] = o[q] + bo[q];
    }
}

// ------------------- launch -------------------
extern "C" void kernel_launch(void* const* d_in, const int* in_sizes, int n_in,
                              void* d_out, int out_size) {
    int cur = 0;
    auto nxt = [&]() -> const void* {
        while (cur < n_in && in_sizes[cur] == 1) cur++;
        return d_in[cur++];
    };
    const float* tf     = (const float*)nxt();
    (void)nxt();                                 // edge_index (structural, unused)
    const float* tw     = (const float*)nxt();
    const float* ff     = (const float*)nxt();
    const float* fw     = (const float*)nxt();
    const int*   labels = (const int*)nxt();
    const float* Wt     = (const float*)nxt();
    const float* bt     = (const float*)nxt();
    const float* Wf     = (const float*)nxt();
    const float* bf     = (const float*)nxt();
    const float* Wc     = (const float*)nxt();
    const float* bc     = (const float*)nxt();
    const float* Wo     = (const float*)nxt();
    const float* bo     = (const float*)nxt();
    float* out = (float*)d_out;

    k_init<<<64, 256>>>(labels);                  // idx 0
    k_xw<<<dim3(32, 2), 256>>>(tf, ff, Wt, Wf);   // idx 1
    k_deg<<<dim3(8, 32, 2), 256>>>(tw, fw);       // idx 2
    k_gcn1<<<dim3(16, 16, 2), 256>>>(tw, fw);     // idx 3  <- ncu capture slot
    k_fcwfin<<<128, 256>>>(bt, bf, Wc);           // idx 4
    k_dist<<<528, 512>>>();                       // idx 5
    k_gcn2<<<dim3(32, 16), 256>>>();              // idx 6
    k_out<<<256, 256>>>(bc, Wo, bo, out);         // idx 7
}